// round 1
// baseline (speedup 1.0000x reference)
#include <cuda_runtime.h>
#include <math.h>

// ---------------------------------------------------------------------------
// Problem constants
// ---------------------------------------------------------------------------
#define T_STEPS 128
#define IN_D    512
#define H_D     512
#define B_D     256
#define TAG     64
#define LM_D    200
#define POS_D   6
#define CAP_D   3
#define HB      (H_D * B_D)          // 131072
#define GATE_M  (4 * H_D)            // 2048
#define TI_M    (3 * H_D)            // 1536
#define GB_M    (GATE_M + TI_M)      // 3584

// Output section offsets (floats) in d_out: lf, lc, y_fact, y_cond, Ts
#define SEC_Y   ((size_t)B_D * T_STEPS * TAG)       // 2,097,152
#define OFF_LF  ((size_t)0)
#define OFF_LC  (SEC_Y)
#define OFF_YF  (2 * SEC_Y)
#define OFF_YC  (3 * SEC_Y)
#define OFF_TS  (4 * SEC_Y)

// ---------------------------------------------------------------------------
// Scratch (device globals; no allocations allowed)
// ---------------------------------------------------------------------------
__device__ float g_x   [(size_t)T_STEPS * IN_D  * B_D];   //  67 MB
__device__ float g_ii  [(size_t)T_STEPS * GATE_M * B_D];  // 268 MB
__device__ float g_tadd[(size_t)T_STEPS * H_D  * B_D];    //  67 MB
__device__ float g_Ts  [(size_t)T_STEPS * H_D  * B_D];    //  67 MB
__device__ float g_gbuf[(size_t)GB_M * B_D];              // hi (2048 rows) + ti (1536 rows)
__device__ float g_c   [HB];
__device__ float g_h   [HB];
__device__ float g_opre[HB];

__device__ __forceinline__ float sigm(float x) { return 1.f / (1.f + expf(-x)); }

// ---------------------------------------------------------------------------
// Generic tiled SGEMM tile accumulator.
// C tile = A (MxK) @ B (KxN), A row-major (or transposed, AT=true: A is KxM).
// 256 threads/CTA. Thread (tx = tid%16, ty = tid/16) owns a TMxTN sub-tile.
// K is bound-checked (zero fill) so K need not be a multiple of BK.
// M tile and N tile are assumed fully in range (all our dims are multiples).
// ---------------------------------------------------------------------------
template <int BM, int BN, int BK, int TM, int TN, bool AT>
__device__ __forceinline__ void gemm_tile(const float* __restrict__ A,
                                          const float* __restrict__ B,
                                          int K, int lda, int ldb,
                                          int m0, int n0,
                                          float (&acc)[TM][TN], float* sm)
{
    static_assert((BM / TM) * (BN / TN) == 256, "256 threads required");
    float (*As)[BM] = (float (*)[BM])sm;
    float (*Bs)[BN] = (float (*)[BN])(sm + BK * BM);
    const int tid = threadIdx.x;
    const int tx  = tid % (BN / TN);
    const int ty  = tid / (BN / TN);
    constexpr int LA = (BM * BK) / 256;
    constexpr int LB = (BK * BN) / 256;

    for (int k0 = 0; k0 < K; k0 += BK) {
#pragma unroll
        for (int i = 0; i < LA; i++) {
            int li = tid + i * 256;
            if (AT) {
                int k = li / BM, m = li % BM;
                int kk = k0 + k;
                As[k][m] = (kk < K) ? A[(size_t)kk * lda + (m0 + m)] : 0.f;
            } else {
                int m = li / BK, k = li % BK;
                int kk = k0 + k;
                As[k][m] = (kk < K) ? A[(size_t)(m0 + m) * lda + kk] : 0.f;
            }
        }
#pragma unroll
        for (int i = 0; i < LB; i++) {
            int li = tid + i * 256;
            int k = li / BN, n = li % BN;
            int kk = k0 + k;
            Bs[k][n] = (kk < K) ? B[(size_t)kk * ldb + (n0 + n)] : 0.f;
        }
        __syncthreads();
#pragma unroll
        for (int k = 0; k < BK; k++) {
            float av[TM], bv[TN];
#pragma unroll
            for (int i = 0; i < TM; i++) av[i] = As[k][ty * TM + i];
#pragma unroll
            for (int j = 0; j < TN; j++) bv[j] = Bs[k][tx * TN + j];
#pragma unroll
            for (int i = 0; i < TM; i++)
#pragma unroll
                for (int j = 0; j < TN; j++) acc[i][j] += av[i] * bv[j];
        }
        __syncthreads();
    }
}

// ---------------------------------------------------------------------------
// Phase A kernels (parallel over t)
// ---------------------------------------------------------------------------

// x[t,i,b] = inputs + w_lmw^T@lm + w_posw^T@pos + w_capw^T@cap
__global__ void __launch_bounds__(256)
k_x(const float* __restrict__ inputs, const float* __restrict__ lms,
    const float* __restrict__ poses, const float* __restrict__ caps,
    const float* __restrict__ w_lmw, const float* __restrict__ w_posw,
    const float* __restrict__ w_capw)
{
    __shared__ float sm[16 * 128];
    int t = blockIdx.z, m0 = blockIdx.y * 64, n0 = blockIdx.x * 64;
    float acc[4][4] = {};
    gemm_tile<64,64,16,4,4,true>(w_lmw,  lms   + (size_t)t * LM_D  * B_D, LM_D,  IN_D, B_D, m0, n0, acc, sm);
    gemm_tile<64,64,16,4,4,true>(w_posw, poses + (size_t)t * POS_D * B_D, POS_D, IN_D, B_D, m0, n0, acc, sm);
    gemm_tile<64,64,16,4,4,true>(w_capw, caps  + (size_t)t * CAP_D * B_D, CAP_D, IN_D, B_D, m0, n0, acc, sm);
    int tx = threadIdx.x % 16, ty = threadIdx.x / 16;
    size_t base = (size_t)t * IN_D * B_D;
#pragma unroll
    for (int i = 0; i < 4; i++)
#pragma unroll
        for (int j = 0; j < 4; j++) {
            size_t idx = base + (size_t)(m0 + ty * 4 + i) * B_D + (n0 + tx * 4 + j);
            g_x[idx] = acc[i][j] + inputs[idx];
        }
}

// t_add[t,h,b] = w_lmt@lm + w_post@pos + w_capt@cap
__global__ void __launch_bounds__(256)
k_tadd(const float* __restrict__ lms, const float* __restrict__ poses,
       const float* __restrict__ caps, const float* __restrict__ w_lmt,
       const float* __restrict__ w_post, const float* __restrict__ w_capt)
{
    __shared__ float sm[16 * 128];
    int t = blockIdx.z, m0 = blockIdx.y * 64, n0 = blockIdx.x * 64;
    float acc[4][4] = {};
    gemm_tile<64,64,16,4,4,false>(w_lmt,  lms   + (size_t)t * LM_D  * B_D, LM_D,  LM_D,  B_D, m0, n0, acc, sm);
    gemm_tile<64,64,16,4,4,false>(w_post, poses + (size_t)t * POS_D * B_D, POS_D, POS_D, B_D, m0, n0, acc, sm);
    gemm_tile<64,64,16,4,4,false>(w_capt, caps  + (size_t)t * CAP_D * B_D, CAP_D, CAP_D, B_D, m0, n0, acc, sm);
    int tx = threadIdx.x % 16, ty = threadIdx.x / 16;
    size_t base = (size_t)t * H_D * B_D;
#pragma unroll
    for (int i = 0; i < 4; i++)
#pragma unroll
        for (int j = 0; j < 4; j++)
            g_tadd[base + (size_t)(m0 + ty * 4 + i) * B_D + (n0 + tx * 4 + j)] = acc[i][j];
}

// ii_all[t] = w_ii @ x[t]
__global__ void __launch_bounds__(256)
k_ii(const float* __restrict__ w_ii)
{
    __shared__ float sm[16 * 128];
    int t = blockIdx.z, m0 = blockIdx.y * 64, n0 = blockIdx.x * 64;
    float acc[4][4] = {};
    gemm_tile<64,64,16,4,4,false>(w_ii, g_x + (size_t)t * IN_D * B_D, IN_D, IN_D, B_D, m0, n0, acc, sm);
    int tx = threadIdx.x % 16, ty = threadIdx.x / 16;
    size_t base = (size_t)t * GATE_M * B_D;
#pragma unroll
    for (int i = 0; i < 4; i++)
#pragma unroll
        for (int j = 0; j < 4; j++)
            g_ii[base + (size_t)(m0 + ty * 4 + i) * B_D + (n0 + tx * 4 + j)] = acc[i][j];
}

// ---------------------------------------------------------------------------
// Recurrent step kernels
// ---------------------------------------------------------------------------

// gbuf[0:2048)   = w_hi @ h_prev
// gbuf[2048:3584) = w_ti @ T_prev
__global__ void __launch_bounds__(256)
k_hi_ti(const float* __restrict__ w_hi, const float* __restrict__ w_ti,
        const float* __restrict__ t0, int t)
{
    __shared__ float sm[16 * 128];
    int n0 = blockIdx.x * 64, m0 = blockIdx.y * 64;
    const float* Tprev = (t == 0) ? t0 : (g_Ts + (size_t)(t - 1) * HB);
    float acc[4][4] = {};
    if (m0 < GATE_M)
        gemm_tile<64,64,16,4,4,false>(w_hi, g_h,   H_D, H_D, B_D, m0,          n0, acc, sm);
    else
        gemm_tile<64,64,16,4,4,false>(w_ti, Tprev, H_D, H_D, B_D, m0 - GATE_M, n0, acc, sm);
    int tx = threadIdx.x % 16, ty = threadIdx.x / 16;
#pragma unroll
    for (int i = 0; i < 4; i++)
#pragma unroll
        for (int j = 0; j < 4; j++)
            g_gbuf[(size_t)(m0 + ty * 4 + i) * B_D + (n0 + tx * 4 + j)] = acc[i][j];
}

// gates + c update (+ o pre-activation)
__global__ void __launch_bounds__(256)
k_gate(const float* __restrict__ b_i, int t)
{
    int idx = blockIdx.x * 256 + threadIdx.x;     // over H*B
    int r = idx >> 8, b = idx & 255;
    const float* iit = g_ii + (size_t)t * GATE_M * B_D;
    int rb = r * B_D + b;

    float pi = iit[rb]                    + g_gbuf[rb]                    + g_gbuf[(size_t)(GATE_M + r) * B_D + b]              + b_i[r];
    float pf = iit[(size_t)(H_D + r)*B_D + b]   + g_gbuf[(size_t)(H_D + r)*B_D + b]   + g_gbuf[(size_t)(GATE_M + H_D + r)*B_D + b]   + b_i[H_D + r];
    float pz = iit[(size_t)(2*H_D + r)*B_D + b] + g_gbuf[(size_t)(2*H_D + r)*B_D + b] + g_gbuf[(size_t)(GATE_M + 2*H_D + r)*B_D + b] + b_i[2*H_D + r];

    float ig = sigm(pi), fg = sigm(pf), zg = tanhf(pz);
    float cn = fg * g_c[idx] + ig * zg;
    g_c[idx] = cn;
    g_opre[idx] = iit[(size_t)(3*H_D + r) * B_D + b] + g_gbuf[(size_t)(3*H_D + r) * B_D + b] + b_i[3*H_D + r];
}

// acc = w_co @ c_new;  o = sigm(opre + acc);  h = o * tanh(c_new)
__global__ void __launch_bounds__(256)
k_co(const float* __restrict__ w_co)
{
    __shared__ float sm[16 * 64];
    int n0 = blockIdx.x * 32, m0 = blockIdx.y * 32;
    float acc[2][2] = {};
    gemm_tile<32,32,16,2,2,false>(w_co, g_c, H_D, H_D, B_D, m0, n0, acc, sm);
    int tx = threadIdx.x % 16, ty = threadIdx.x / 16;
#pragma unroll
    for (int i = 0; i < 2; i++)
#pragma unroll
        for (int j = 0; j < 2; j++) {
            int rb = (m0 + ty * 2 + i) * B_D + (n0 + tx * 2 + j);
            float o = sigm(g_opre[rb] + acc[i][j]);
            g_h[rb] = o * tanhf(g_c[rb]);
        }
}

// T_new = w_ht @ h_new + b[4H:] + t_add[t]; stored as Ts[t] (doubles as T state)
__global__ void __launch_bounds__(256)
k_ht(const float* __restrict__ w_ht, const float* __restrict__ b_i, int t)
{
    __shared__ float sm[16 * 64];
    int n0 = blockIdx.x * 32, m0 = blockIdx.y * 32;
    float acc[2][2] = {};
    gemm_tile<32,32,16,2,2,false>(w_ht, g_h, H_D, H_D, B_D, m0, n0, acc, sm);
    int tx = threadIdx.x % 16, ty = threadIdx.x / 16;
    size_t base = (size_t)t * HB;
#pragma unroll
    for (int i = 0; i < 2; i++)
#pragma unroll
        for (int j = 0; j < 2; j++) {
            int r = m0 + ty * 2 + i, c = n0 + tx * 2 + j;
            g_Ts[base + (size_t)r * B_D + c] = acc[i][j] + b_i[4 * H_D + r] + g_tadd[base + (size_t)r * B_D + c];
        }
}

// ---------------------------------------------------------------------------
// Phase C kernels
// ---------------------------------------------------------------------------

// Tag heads + log_softmax, direct (b,t,y) layout writes
__global__ void __launch_bounds__(256)
k_y(const float* __restrict__ wyf, const float* __restrict__ byf,
    const float* __restrict__ wyc, const float* __restrict__ byc,
    float* __restrict__ out)
{
    __shared__ float sm[2 * 64 * 68];   // also used as GEMM smem (needs 2048)
    int t = blockIdx.y, n0 = blockIdx.x * 64;
    const float* Tst = g_Ts + (size_t)t * HB;
    float aF[4][4] = {}, aC[4][4] = {};
    gemm_tile<64,64,16,4,4,false>(wyf, Tst, H_D, H_D, B_D, 0, n0, aF, sm);
    gemm_tile<64,64,16,4,4,false>(wyc, Tst, H_D, H_D, B_D, 0, n0, aC, sm);

    float (*yF)[68] = (float (*)[68])sm;
    float (*yC)[68] = (float (*)[68])(sm + 64 * 68);
    int tx = threadIdx.x % 16, ty = threadIdx.x / 16;
#pragma unroll
    for (int i = 0; i < 4; i++)
#pragma unroll
        for (int j = 0; j < 4; j++) {
            int m = ty * 4 + i, n = tx * 4 + j;
            yF[m][n] = aF[i][j] + byf[m];
            yC[m][n] = aC[i][j] + byc[m];
        }
    __syncthreads();

    if (threadIdx.x < 64) {
        int col = threadIdx.x;
        int b = n0 + col;
        float mxF = -1e30f, mxC = -1e30f;
#pragma unroll
        for (int m = 0; m < TAG; m++) {
            mxF = fmaxf(mxF, yF[m][col]);
            mxC = fmaxf(mxC, yC[m][col]);
        }
        float sF = 0.f, sC = 0.f;
#pragma unroll
        for (int m = 0; m < TAG; m++) {
            sF += expf(yF[m][col] - mxF);
            sC += expf(yC[m][col] - mxC);
        }
        float lseF = mxF + logf(sF);
        float lseC = mxC + logf(sC);
        size_t base = ((size_t)b * T_STEPS + t) * TAG;
#pragma unroll
        for (int m = 0; m < TAG; m++) {
            float vf = yF[m][col], vc = yC[m][col];
            out[OFF_LF + base + m] = vf - lseF;
            out[OFF_LC + base + m] = vc - lseC;
            out[OFF_YF + base + m] = vf;
            out[OFF_YC + base + m] = vc;
        }
    }
}

// Ts (t,h,b) -> out (b,t,h) transpose
__global__ void k_tsout(float* __restrict__ out)
{
    __shared__ float tile[32][33];
    int t = blockIdx.z;
    int b0 = blockIdx.x * 32, h0 = blockIdx.y * 32;
    int tx = threadIdx.x, ty = threadIdx.y;   // 32 x 8
    size_t base = (size_t)t * HB;
    for (int i = ty; i < 32; i += 8)
        tile[i][tx] = g_Ts[base + (size_t)(h0 + i) * B_D + (b0 + tx)];
    __syncthreads();
    for (int i = ty; i < 32; i += 8)
        out[OFF_TS + ((size_t)(b0 + i) * T_STEPS + t) * H_D + (h0 + tx)] = tile[tx][i];
}

// Initialize h, c states from inputs
__global__ void k_init(const float* __restrict__ h0, const float* __restrict__ c0)
{
    int i = blockIdx.x * 256 + threadIdx.x;
    if (i < HB) { g_h[i] = h0[i]; g_c[i] = c0[i]; }
}

// ---------------------------------------------------------------------------
// Launch
// ---------------------------------------------------------------------------
extern "C" void kernel_launch(void* const* d_in, const int* in_sizes, int n_in,
                              void* d_out, int out_size)
{
    const float* inputs   = (const float*)d_in[0];
    const float* lms      = (const float*)d_in[1];
    const float* poses    = (const float*)d_in[2];
    const float* caps     = (const float*)d_in[3];
    const float* h0       = (const float*)d_in[4];
    const float* c0       = (const float*)d_in[5];
    const float* t0       = (const float*)d_in[6];
    const float* w_ii     = (const float*)d_in[7];
    const float* w_hi     = (const float*)d_in[8];
    const float* w_ti     = (const float*)d_in[9];
    const float* w_co     = (const float*)d_in[10];
    const float* w_ht     = (const float*)d_in[11];
    const float* b_i      = (const float*)d_in[12];
    const float* w_y_fact = (const float*)d_in[13];
    const float* b_y_fact = (const float*)d_in[14];
    const float* w_y_cond = (const float*)d_in[15];
    const float* b_y_cond = (const float*)d_in[16];
    const float* w_lmw    = (const float*)d_in[17];
    const float* w_posw   = (const float*)d_in[18];
    const float* w_capw   = (const float*)d_in[19];
    const float* w_lmt    = (const float*)d_in[20];
    const float* w_post   = (const float*)d_in[21];
    const float* w_capt   = (const float*)d_in[22];
    float* out = (float*)d_out;

    k_init<<<HB / 256, 256>>>(h0, c0);
    k_x   <<<dim3(B_D / 64, IN_D / 64, T_STEPS), 256>>>(inputs, lms, poses, caps, w_lmw, w_posw, w_capw);
    k_tadd<<<dim3(B_D / 64, H_D / 64, T_STEPS), 256>>>(lms, poses, caps, w_lmt, w_post, w_capt);
    k_ii  <<<dim3(B_D / 64, GATE_M / 64, T_STEPS), 256>>>(w_ii);

    for (int t = 0; t < T_STEPS; t++) {
        k_hi_ti<<<dim3(B_D / 64, GB_M / 64), 256>>>(w_hi, w_ti, t0, t);
        k_gate <<<HB / 256, 256>>>(b_i, t);
        k_co   <<<dim3(B_D / 32, H_D / 32), 256>>>(w_co);
        k_ht   <<<dim3(B_D / 32, H_D / 32), 256>>>(w_ht, b_i, t);
    }

    k_y    <<<dim3(B_D / 64, T_STEPS), 256>>>(w_y_fact, b_y_fact, w_y_cond, b_y_cond, out);
    k_tsout<<<dim3(B_D / 32, H_D / 32, T_STEPS), dim3(32, 8)>>>(out);
}